// round 9
// baseline (speedup 1.0000x reference)
#include <cuda_runtime.h>
#include <cuda_bf16.h>
#include <math.h>
#include <stdint.h>

#define NNODE 20000
#define NEDGE 640000
#define MUL 32
#define FC 64
#define SCAL 16

#define INV_MUL  0.17677669529663687f
#define INV_FC   0.125f
#define INV_SCAL 0.25f
#define INV_SQ3  0.57735026918962576f
#define COS_A    0.92387953251128674f
#define SIN_A    0.38268343236508978f
#define INV_NB   0.17677669529663687f
#define INV_MID  0.125f

#define NWARP 12
#define NTHR  (NWARP * 32)

typedef unsigned long long u64;

// ---------------- device scratch ----------------
__device__ float  g_feat[NNODE * 128];      // [N]: [0..32)=fs, [32+c*32+u]=fv
__device__ float  g_ss[NNODE * MUL];
__device__ float  g_sv[NNODE * MUL * 3];    // [N][32][3]
__device__ float4 g_ns_mid[NNODE * 16];     // [N][64]
__device__ float4 g_nv_mid[NNODE * 48];     // [N][3][64]

// ---------------- packed f32x2 helpers ----------------
__device__ __forceinline__ u64 pk2(float lo, float hi) {
    u64 r; asm("mov.b64 %0,{%1,%2};" : "=l"(r) : "f"(lo), "f"(hi)); return r;
}
__device__ __forceinline__ float2 upk2(u64 v) {
    float2 f; asm("mov.b64 {%0,%1},%2;" : "=f"(f.x), "=f"(f.y) : "l"(v)); return f;
}
__device__ __forceinline__ u64 f2fma(u64 a, u64 b, u64 c) {
    u64 d; asm("fma.rn.f32x2 %0,%1,%2,%3;" : "=l"(d) : "l"(a), "l"(b), "l"(c)); return d;
}
__device__ __forceinline__ u64 f2mul(u64 a, u64 b) {
    u64 d; asm("mul.rn.f32x2 %0,%1,%2;" : "=l"(d) : "l"(a), "l"(b)); return d;
}
__device__ __forceinline__ u64 f2add(u64 a, u64 b) {
    u64 d; asm("add.rn.f32x2 %0,%1,%2;" : "=l"(d) : "l"(a), "l"(b)); return d;
}
__device__ __forceinline__ float tanh_ap(float x) {
    float y; asm("tanh.approx.f32 %0,%1;" : "=f"(y) : "f"(x)); return y;
}
__device__ __forceinline__ u64 gelu2(float s0, float s1) {
    const u64 C1D = pk2(0.79788456080286535588f, 0.79788456080286535588f);
    const u64 C2D = pk2(0.03567740813636141f, 0.03567740813636141f);
    u64 x = pk2(s0, s1);
    u64 x2 = f2mul(x, x);
    u64 arg = f2mul(x, f2fma(x2, C2D, C1D));
    float2 a = upk2(arg);
    u64 tp = pk2(tanh_ap(a.x), tanh_ap(a.y));
    return f2mul(f2mul(x, pk2(0.5f, 0.5f)), f2add(pk2(1.f, 1.f), tp));
}
__device__ __forceinline__ float dot16p(const u64 x[8], const float* w) {
    const ulonglong2* w2 = reinterpret_cast<const ulonglong2*>(w);
    u64 a0 = 0ULL, a1 = 0ULL;
#pragma unroll
    for (int k = 0; k < 4; ++k) {
        ulonglong2 wv = w2[k];
        a0 = f2fma(x[2 * k], wv.x, a0);
        a1 = f2fma(x[2 * k + 1], wv.y, a1);
    }
    float2 s = upk2(f2add(a0, a1));
    return s.x + s.y;
}
__device__ __forceinline__ void red4(float4* addr, float4 v) {
    asm volatile("red.global.add.v4.f32 [%0], {%1,%2,%3,%4};"
                 :: "l"(addr), "f"(v.x), "f"(v.y), "f"(v.z), "f"(v.w) : "memory");
}
__device__ __forceinline__ uint32_t smem_u32(const void* p) {
    uint32_t a;
    asm("{ .reg .u64 t; cvta.to.shared.u64 t, %1; cvt.u32.u64 %0, t; }" : "=r"(a) : "l"(p));
    return a;
}

// ---------------- mma / ldmatrix macros (base sm_100 ISA) ----------------
#define MMA_BF16(c, a, b0, b1) \
    asm volatile("mma.sync.aligned.m16n8k16.row.col.f32.bf16.bf16.f32 " \
        "{%0,%1,%2,%3}, {%4,%5,%6,%7}, {%8,%9}, {%0,%1,%2,%3};" \
        : "+f"((c)[0]), "+f"((c)[1]), "+f"((c)[2]), "+f"((c)[3]) \
        : "r"((a)[0]), "r"((a)[1]), "r"((a)[2]), "r"((a)[3]), "r"(b0), "r"(b1))

#define LDSM4(r, addr) \
    asm volatile("ldmatrix.sync.aligned.m8n8.x4.shared.b16 {%0,%1,%2,%3}, [%4];" \
        : "=r"((r)[0]), "=r"((r)[1]), "=r"((r)[2]), "=r"((r)[3]) : "r"(addr))

#define LDSM2(r0, r1, addr) \
    asm volatile("ldmatrix.sync.aligned.m8n8.x2.shared.b16 {%0,%1}, [%2];" \
        : "=r"(r0), "=r"(r1) : "r"(addr))

// smem byte layout
#define SMB_W0    0        // 4096  : W0^T [64][16] f32, scaled
#define SMB_B1HI  4096     // 9216  : L1 weights^T [64 n][72 k] bf16 hi
#define SMB_B1LO  13312    // 9216
#define SMB_BHHI  22528    // 18432 : head weights^T [128 n][72 k] bf16 hi
#define SMB_BHLO  40960    // 18432
#define SMB_WBUF  59392    // per-warp regions
// per-warp: [0,9216) h0 hi/lo planes, aliased by Cbuf [0,8704)
//           [9216,9728) escal | [9728,9856) sdst | [9856,9984) ssrc
#define WARP_SMEM 9984
#define SM_TOTAL  (59392 + NWARP * WARP_SMEM)   // 179200

// ---------------- kernel A: node linear 1 + zero accumulators ----------------
__global__ void __launch_bounds__(256, 3)
node_pre_kernel(const float* __restrict__ node_s,
                const float* __restrict__ node_v,
                const float* __restrict__ W1sf,
                const float* __restrict__ W1ss,
                const float* __restrict__ W1vf,
                const float* __restrict__ W1vs) {
    __shared__ float sWsf[1024], sWss[1024], sWvf[1024], sWvs[1024];
    for (int i = threadIdx.x; i < 1024; i += blockDim.x) {
        sWsf[i] = W1sf[i]; sWss[i] = W1ss[i];
        sWvf[i] = W1vf[i]; sWvs[i] = W1vs[i];
    }
    __syncthreads();
    int base = blockIdx.x * blockDim.x + threadIdx.x;
    const int STRIDE = 160000;
    const int TOT4 = NNODE * 64;
    for (int i = base; i < TOT4; i += STRIDE) {
        if (i < NNODE * 16) g_ns_mid[i] = make_float4(0.f, 0.f, 0.f, 0.f);
        else                g_nv_mid[i - NNODE * 16] = make_float4(0.f, 0.f, 0.f, 0.f);
    }
    for (int tid = base; tid < NNODE * MUL; tid += STRIDE) {
        int n = tid >> 5, v = tid & 31;
        float afs = 0.f, ass = 0.f;
        float fv0 = 0.f, fv1 = 0.f, fv2 = 0.f;
        float sv0 = 0.f, sv1 = 0.f, sv2 = 0.f;
#pragma unroll 8
        for (int u = 0; u < 32; ++u) {
            float s = node_s[n * 32 + u];
            afs += s * sWsf[u * 32 + v];
            ass += s * sWss[u * 32 + v];
            float c0 = node_v[(n * 32 + u) * 3 + 0];
            float c1 = node_v[(n * 32 + u) * 3 + 1];
            float c2 = node_v[(n * 32 + u) * 3 + 2];
            float wf = sWvf[u * 32 + v];
            float ws = sWvs[u * 32 + v];
            fv0 += c0 * wf; fv1 += c1 * wf; fv2 += c2 * wf;
            sv0 += c0 * ws; sv1 += c1 * ws; sv2 += c2 * ws;
        }
        g_feat[n * 128 + v]            = INV_MUL * afs;
        g_ss[n * 32 + v]               = INV_MUL * ass;
        g_feat[n * 128 + 32 + v]       = INV_MUL * fv0;
        g_feat[n * 128 + 64 + v]       = INV_MUL * fv1;
        g_feat[n * 128 + 96 + v]       = INV_MUL * fv2;
        g_sv[(n * 32 + v) * 3 + 0] = INV_MUL * sv0;
        g_sv[(n * 32 + v) * 3 + 1] = INV_MUL * sv1;
        g_sv[(n * 32 + v) * 3 + 2] = INV_MUL * sv2;
    }
}

// ---------------- kernel B: edge MLP (SIMT L0 + mma) + coalesced scatter ----------------
__global__ void __launch_bounds__(NTHR, 1)
edge_kernel(const float* __restrict__ esa,
            const float* __restrict__ eattr_s,
            const float* __restrict__ eattr_v,
            const int*   __restrict__ e_src,
            const int*   __restrict__ e_dst,
            const float* __restrict__ Wm0,
            const float* __restrict__ Wm1,
            const float* __restrict__ Wi0g,
            const float* __restrict__ Wi1g,
            const float* __restrict__ Wi2g,
            const float* __restrict__ Wi3g) {
    extern __shared__ char smc[];
    float* sW0 = reinterpret_cast<float*>(smc + SMB_W0);
    const int tid = threadIdx.x;
    const int lane = tid & 31;
    const int wid = tid >> 5;
    uint32_t sbase = smem_u32(smc);

    for (int i = tid; i < 1024; i += NTHR) {
        int j = i >> 4, k = i & 15;
        sW0[j * 16 + k] = INV_SCAL * Wm0[k * 64 + j];
    }
    for (int i = tid; i < 4096; i += NTHR) {
        int n = i >> 6, k = i & 63;
        float v = INV_FC * Wm1[k * 64 + n];
        __nv_bfloat16 hi = __float2bfloat16(v);
        __nv_bfloat16 lo = __float2bfloat16(v - __bfloat162float(hi));
        *reinterpret_cast<__nv_bfloat16*>(smc + SMB_B1HI + n * 144 + k * 2) = hi;
        *reinterpret_cast<__nv_bfloat16*>(smc + SMB_B1LO + n * 144 + k * 2) = lo;
    }
    {
        const float* gW[4] = {Wi0g, Wi1g, Wi2g, Wi3g};
        const float  gS[4] = {INV_FC, INV_FC, INV_FC, INV_FC * INV_SQ3};
        for (int i = tid; i < 8192; i += NTHR) {
            int n = i >> 6, k = i & 63;
            int h = n >> 5, u = n & 31;
            float v = gS[h] * gW[h][k * 32 + u];
            __nv_bfloat16 hi = __float2bfloat16(v);
            __nv_bfloat16 lo = __float2bfloat16(v - __bfloat162float(hi));
            *reinterpret_cast<__nv_bfloat16*>(smc + SMB_BHHI + n * 144 + k * 2) = hi;
            *reinterpret_cast<__nv_bfloat16*>(smc + SMB_BHLO + n * 144 + k * 2) = lo;
        }
    }
    __syncthreads();

    char*  wreg  = smc + SMB_WBUF + wid * WARP_SMEM;
    char*  bufhi = wreg;                              // h0 hi plane (phase 1)
    char*  buflo = wreg + 4608;                       // h0 lo plane
    float* CbufF = reinterpret_cast<float*>(wreg);    // C readback 32 x 68 f32 (alias)
    float4* escal = reinterpret_cast<float4*>(wreg + 9216);  // 32 x float4
    int*   sdst  = reinterpret_cast<int*>(wreg + 9728);      // 32 x int
    int*   ssrc  = reinterpret_cast<int*>(wreg + 9856);      // 32 x int
    uint32_t a0base = sbase + SMB_WBUF + wid * WARP_SMEM;

    const int idx16 = lane & 15;
    const int brow = idx16 & 7;
    const int bkof = ((idx16 >> 3) & 1) << 4;
    const int role = lane >> 3;
    const int idx  = lane & 7;

    const int NCHUNK = NEDGE / 32;              // 20000
    const int WSTRIDE = 148 * NWARP;

    for (int chunk = blockIdx.x * NWARP + wid; chunk < NCHUNK; chunk += WSTRIDE) {
        int e = chunk * 32 + lane;

        // ---- per-edge metadata early (overlaps MLP compute)
        int src = e_src[e];
        int dst = e_dst[e];
        float eas = eattr_s[e];
        float av0 = eattr_v[3 * e + 0];
        float av1 = eattr_v[3 * e + 1];
        float av2 = eattr_v[3 * e + 2];
        escal[lane] = make_float4(eas, av0, av1, av2);
        sdst[lane] = dst;
        ssrc[lane] = src;

        // ---- L0 SIMT fused: dot -> gelu -> split -> store (no hp0 array)
        const ulonglong2* xq = reinterpret_cast<const ulonglong2*>(esa + (size_t)e * 16);
        ulonglong2 q0 = xq[0], q1 = xq[1], q2 = xq[2], q3 = xq[3];
        u64 xp[8] = {q0.x, q0.y, q1.x, q1.y, q2.x, q2.y, q3.x, q3.y};
#pragma unroll 4
        for (int j = 0; j < 32; j += 2) {
            float s0 = dot16p(xp, sW0 + (2 * j) * 16);
            float s1 = dot16p(xp, sW0 + (2 * j + 1) * 16);
            float s2 = dot16p(xp, sW0 + (2 * j + 2) * 16);
            float s3 = dot16p(xp, sW0 + (2 * j + 3) * 16);
            float2 p0 = upk2(gelu2(s0, s1));
            float2 p1 = upk2(gelu2(s2, s3));
            __nv_bfloat162 h0a = __float22bfloat162_rn(p0);
            __nv_bfloat162 h0b = __float22bfloat162_rn(p1);
            float2 f0 = __bfloat1622float2(h0a);
            float2 f1 = __bfloat1622float2(h0b);
            __nv_bfloat162 l0a = __float22bfloat162_rn(make_float2(p0.x - f0.x, p0.y - f0.y));
            __nv_bfloat162 l0b = __float22bfloat162_rn(make_float2(p1.x - f1.x, p1.y - f1.y));
            uint32_t ha = *reinterpret_cast<uint32_t*>(&h0a);
            uint32_t hb = *reinterpret_cast<uint32_t*>(&h0b);
            uint32_t la = *reinterpret_cast<uint32_t*>(&l0a);
            uint32_t lb = *reinterpret_cast<uint32_t*>(&l0b);
            *reinterpret_cast<u64*>(bufhi + lane * 144 + j * 4) = ((u64)hb << 32) | ha;
            *reinterpret_cast<u64*>(buflo + lane * 144 + j * 4) = ((u64)lb << 32) | la;
        }
        __syncwarp();

        // ---- ldmatrix A0 fragments
        uint32_t A0h[2][4][4], A0l[2][4][4];
#pragma unroll
        for (int m = 0; m < 2; ++m)
#pragma unroll
            for (int k = 0; k < 4; ++k) {
                uint32_t addr = a0base
                    + (uint32_t)((m * 16 + (lane & 7) + ((lane >> 3) & 1) * 8) * 144)
                    + (uint32_t)(k * 32 + ((lane >> 4) & 1) * 16);
                LDSM4(A0h[m][k], addr);
                LDSM4(A0l[m][k], addr + 4608);
            }
        __syncwarp();

        // ---- L1 mma (3-pass hi/lo)
        float C1[2][8][4];
#pragma unroll
        for (int m = 0; m < 2; ++m)
#pragma unroll
            for (int n = 0; n < 8; ++n)
#pragma unroll
                for (int q = 0; q < 4; ++q) C1[m][n][q] = 0.f;
#pragma unroll
        for (int n = 0; n < 8; ++n)
#pragma unroll
            for (int k = 0; k < 4; ++k) {
                uint32_t baddr = sbase + SMB_B1HI
                    + (uint32_t)((n * 8 + brow) * 144) + (uint32_t)(k * 32) + bkof;
                uint32_t bh0, bh1, bl0, bl1;
                LDSM2(bh0, bh1, baddr);
                LDSM2(bl0, bl1, baddr + 9216);
#pragma unroll
                for (int m = 0; m < 2; ++m) {
                    MMA_BF16(C1[m][n], A0h[m][k], bh0, bh1);
                    MMA_BF16(C1[m][n], A0l[m][k], bh0, bh1);
                    MMA_BF16(C1[m][n], A0h[m][k], bl0, bl1);
                }
            }

        // ---- gelu in-fragment -> heads A fragments
        uint32_t A1h[2][4][4], A1l[2][4][4];
#pragma unroll
        for (int m = 0; m < 2; ++m)
#pragma unroll
            for (int k = 0; k < 4; ++k) {
#pragma unroll
                for (int half = 0; half < 2; ++half) {
                    const float* cp = C1[m][2 * k + half];
#pragma unroll
                    for (int pp = 0; pp < 2; ++pp) {
                        float2 p = upk2(gelu2(cp[2 * pp], cp[2 * pp + 1]));
                        __nv_bfloat162 hi2 = __float22bfloat162_rn(p);
                        float2 hf = __bfloat1622float2(hi2);
                        __nv_bfloat162 lo2 =
                            __float22bfloat162_rn(make_float2(p.x - hf.x, p.y - hf.y));
                        A1h[m][k][half * 2 + pp] = *reinterpret_cast<uint32_t*>(&hi2);
                        A1l[m][k][half * 2 + pp] = *reinterpret_cast<uint32_t*>(&lo2);
                    }
                }
            }

        // ---- heads in two 64-col chunks, transposed epilogue (direct gather)
#pragma unroll
        for (int nh = 0; nh < 2; ++nh) {
            float C[2][8][4];
#pragma unroll
            for (int m = 0; m < 2; ++m)
#pragma unroll
                for (int n = 0; n < 8; ++n)
#pragma unroll
                    for (int q = 0; q < 4; ++q) C[m][n][q] = 0.f;
#pragma unroll
            for (int n = 0; n < 8; ++n)
#pragma unroll
                for (int k = 0; k < 4; ++k) {
                    uint32_t baddr = sbase + SMB_BHHI
                        + (uint32_t)(((nh * 8 + n) * 8 + brow) * 144)
                        + (uint32_t)(k * 32) + bkof;
                    uint32_t bh0, bh1, bl0, bl1;
                    LDSM2(bh0, bh1, baddr);
                    LDSM2(bl0, bl1, baddr + 18432);
#pragma unroll
                    for (int m = 0; m < 2; ++m) {
                        MMA_BF16(C[m][n], A1h[m][k], bh0, bh1);
                        MMA_BF16(C[m][n], A1l[m][k], bh0, bh1);
                        MMA_BF16(C[m][n], A1h[m][k], bl0, bl1);
                    }
                }
            // C -> Cbuf (stride 68 floats)
            __syncwarp();
#pragma unroll
            for (int m = 0; m < 2; ++m)
#pragma unroll
                for (int n = 0; n < 8; ++n) {
                    int row = m * 16 + (lane >> 2);
                    int col = n * 8 + 2 * (lane & 3);
                    *reinterpret_cast<float2*>(CbufF + row * 68 + col) =
                        make_float2(C[m][n][0], C[m][n][1]);
                    *reinterpret_cast<float2*>(CbufF + (row + 8) * 68 + col) =
                        make_float2(C[m][n][2], C[m][n][3]);
                }
            __syncwarp();

            // flattened epilogue: direct coalesced gather from g_feat + red4
#pragma unroll 4
            for (int j = 0; j < 32; ++j) {
                float4 sc = escal[j];
                int dstj = sdst[j];
                const float* fb = g_feat + (size_t)ssrc[j] * 128;
                float4 o;
                float4* addr;
                if (nh == 0) {
                    float4 wch = *reinterpret_cast<const float4*>(
                        CbufF + j * 68 + (role == 0 ? 0 : 32) + idx * 4);
                    float4 esc = *reinterpret_cast<const float4*>(fb + idx * 4);
                    float s = (role == 0) ? sc.x :
                              (role == 1) ? sc.y : (role == 2) ? sc.z : sc.w;
                    o.x = wch.x * esc.x * s; o.y = wch.y * esc.y * s;
                    o.z = wch.z * esc.z * s; o.w = wch.w * esc.w * s;
                    addr = (role == 0) ? (g_ns_mid + dstj * 16 + idx)
                         : (g_nv_mid + dstj * 48 + (role - 1) * 16 + idx);
                } else {
                    if (role < 3) {
                        float4 w2 = *reinterpret_cast<const float4*>(
                            CbufF + j * 68 + idx * 4);
                        float4 ev = *reinterpret_cast<const float4*>(
                            fb + 32 + role * 32 + idx * 4);
                        o.x = w2.x * ev.x * sc.x; o.y = w2.y * ev.y * sc.x;
                        o.z = w2.z * ev.z * sc.x; o.w = w2.w * ev.w * sc.x;
                        addr = g_nv_mid + dstj * 48 + role * 16 + 8 + idx;
                    } else {
                        float4 w3 = *reinterpret_cast<const float4*>(
                            CbufF + j * 68 + 32 + idx * 4);
                        float4 e0 = *reinterpret_cast<const float4*>(fb + 32 + idx * 4);
                        float4 e1 = *reinterpret_cast<const float4*>(fb + 64 + idx * 4);
                        float4 e2 = *reinterpret_cast<const float4*>(fb + 96 + idx * 4);
                        float4 d;
                        d.x = e0.x * sc.y + e1.x * sc.z + e2.x * sc.w;
                        d.y = e0.y * sc.y + e1.y * sc.z + e2.y * sc.w;
                        d.z = e0.z * sc.y + e1.z * sc.z + e2.z * sc.w;
                        d.w = e0.w * sc.y + e1.w * sc.z + e2.w * sc.w;
                        o.x = w3.x * d.x; o.y = w3.y * d.y;
                        o.z = w3.z * d.z; o.w = w3.w * d.w;
                        addr = g_ns_mid + dstj * 16 + 8 + idx;
                    }
                }
                red4(addr, o);
            }
            __syncwarp();
        }
    }
}

// ---------------- kernel C: node linear 2 + mix ----------------
__global__ void __launch_bounds__(256, 3)
node_post_kernel(const float* __restrict__ W2s,
                 const float* __restrict__ W2v,
                 float* __restrict__ out) {
    __shared__ float sW2s[2048], sW2v[2048];
    for (int i = threadIdx.x; i < 2048; i += blockDim.x) {
        sW2s[i] = W2s[i]; sW2v[i] = W2v[i];
    }
    __syncthreads();
    int base = blockIdx.x * blockDim.x + threadIdx.x;
    const int STRIDE = 160000;
    for (int tid = base; tid < NNODE * MUL; tid += STRIDE) {
        int n = tid >> 5, v = tid & 31;
        const float* ms = reinterpret_cast<const float*>(g_ns_mid) + n * 64;
        const float* mv = reinterpret_cast<const float*>(g_nv_mid) + n * 192;
        float cs = 0.f, cv0 = 0.f, cv1 = 0.f, cv2 = 0.f;
#pragma unroll 8
        for (int u = 0; u < 64; ++u) {
            float ws = sW2s[u * 32 + v];
            float wv = sW2v[u * 32 + v];
            cs  += ms[u] * ws;
            cv0 += mv[u]       * wv;
            cv1 += mv[64 + u]  * wv;
            cv2 += mv[128 + u] * wv;
        }
        const float SC = SIN_A * INV_MID * INV_NB;
        out[n * 32 + v] = COS_A * g_ss[n * 32 + v] + SC * cs;
        float* outv = out + NNODE * 32;
        int b = (n * 32 + v) * 3;
        outv[b + 0] = COS_A * g_sv[b + 0] + SC * cv0;
        outv[b + 1] = COS_A * g_sv[b + 1] + SC * cv1;
        outv[b + 2] = COS_A * g_sv[b + 2] + SC * cv2;
    }
}

// ---------------- launch ----------------
extern "C" void kernel_launch(void* const* d_in, const int* in_sizes, int n_in,
                              void* d_out, int out_size) {
    const float *node_s, *node_v, *eattr_s, *eattr_v, *esa;
    const float *W1sf, *W1ss, *W1vf, *W1vs, *Wm0, *Wm1;
    const float *Wi0, *Wi1, *Wi2, *Wi3, *W2s, *W2v;
    const int *e_src, *e_dst;

    node_s  = (const float*)d_in[0];
    node_v  = (const float*)d_in[1];
    eattr_s = (const float*)d_in[2];
    eattr_v = (const float*)d_in[3];
    esa     = (const float*)d_in[4];
    if (in_sizes[5] == NEDGE) {
        e_src = (const int*)d_in[5];
        e_dst = (const int*)d_in[6];
        W1sf = (const float*)d_in[7];  W1ss = (const float*)d_in[8];
        W1vf = (const float*)d_in[9];  W1vs = (const float*)d_in[10];
        Wm0  = (const float*)d_in[11]; Wm1  = (const float*)d_in[12];
        Wi0  = (const float*)d_in[13]; Wi1  = (const float*)d_in[14];
        Wi2  = (const float*)d_in[15]; Wi3  = (const float*)d_in[16];
        W2s  = (const float*)d_in[17]; W2v  = (const float*)d_in[18];
    } else {
        W1sf = (const float*)d_in[5];  W1ss = (const float*)d_in[6];
        W1vf = (const float*)d_in[7];  W1vs = (const float*)d_in[8];
        Wm0  = (const float*)d_in[9];  Wm1  = (const float*)d_in[10];
        Wi0  = (const float*)d_in[11]; Wi1  = (const float*)d_in[12];
        Wi2  = (const float*)d_in[13]; Wi3  = (const float*)d_in[14];
        W2s  = (const float*)d_in[15]; W2v  = (const float*)d_in[16];
        e_src = (const int*)d_in[17];
        e_dst = (const int*)d_in[18];
    }

    cudaFuncSetAttribute(edge_kernel,
                         cudaFuncAttributeMaxDynamicSharedMemorySize, SM_TOTAL);

    node_pre_kernel<<<625, 256>>>(node_s, node_v, W1sf, W1ss, W1vf, W1vs);

    edge_kernel<<<148, NTHR, SM_TOTAL>>>(
        esa, eattr_s, eattr_v, e_src, e_dst, Wm0, Wm1, Wi0, Wi1, Wi2, Wi3);

    node_post_kernel<<<625, 256>>>(W2s, W2v, (float*)d_out);
}

// round 11
// speedup vs baseline: 1.2102x; 1.2102x over previous
#include <cuda_runtime.h>
#include <cuda_bf16.h>
#include <math.h>
#include <stdint.h>

#define NNODE 20000
#define NEDGE 640000
#define MUL 32
#define FC 64
#define SCAL 16

#define INV_MUL  0.17677669529663687f
#define INV_FC   0.125f
#define INV_SCAL 0.25f
#define INV_SQ3  0.57735026918962576f
#define COS_A    0.92387953251128674f
#define SIN_A    0.38268343236508978f
#define INV_NB   0.17677669529663687f
#define INV_MID  0.125f

#define NWARP 12
#define NTHR  (NWARP * 32)

typedef unsigned long long u64;

// ---------------- device scratch ----------------
__device__ float  g_feat[NNODE * 128];      // [N]: [0..32)=fs, [32+c*32+u]=fv
__device__ float  g_ss[NNODE * MUL];
__device__ float  g_sv[NNODE * MUL * 3];    // [N][32][3]
__device__ float4 g_ns_mid[NNODE * 16];     // [N][64]
__device__ float4 g_nv_mid[NNODE * 48];     // [N][3][64]

// ---------------- packed f32x2 helpers ----------------
__device__ __forceinline__ u64 pk2(float lo, float hi) {
    u64 r; asm("mov.b64 %0,{%1,%2};" : "=l"(r) : "f"(lo), "f"(hi)); return r;
}
__device__ __forceinline__ float2 upk2(u64 v) {
    float2 f; asm("mov.b64 {%0,%1},%2;" : "=f"(f.x), "=f"(f.y) : "l"(v)); return f;
}
__device__ __forceinline__ u64 f2fma(u64 a, u64 b, u64 c) {
    u64 d; asm("fma.rn.f32x2 %0,%1,%2,%3;" : "=l"(d) : "l"(a), "l"(b), "l"(c)); return d;
}
__device__ __forceinline__ u64 f2mul(u64 a, u64 b) {
    u64 d; asm("mul.rn.f32x2 %0,%1,%2;" : "=l"(d) : "l"(a), "l"(b)); return d;
}
__device__ __forceinline__ u64 f2add(u64 a, u64 b) {
    u64 d; asm("add.rn.f32x2 %0,%1,%2;" : "=l"(d) : "l"(a), "l"(b)); return d;
}
__device__ __forceinline__ float tanh_ap(float x) {
    float y; asm("tanh.approx.f32 %0,%1;" : "=f"(y) : "f"(x)); return y;
}
__device__ __forceinline__ u64 gelu2(float s0, float s1) {
    const u64 C1D = pk2(0.79788456080286535588f, 0.79788456080286535588f);
    const u64 C2D = pk2(0.03567740813636141f, 0.03567740813636141f);
    u64 x = pk2(s0, s1);
    u64 x2 = f2mul(x, x);
    u64 arg = f2mul(x, f2fma(x2, C2D, C1D));
    float2 a = upk2(arg);
    u64 tp = pk2(tanh_ap(a.x), tanh_ap(a.y));
    return f2mul(f2mul(x, pk2(0.5f, 0.5f)), f2add(pk2(1.f, 1.f), tp));
}
__device__ __forceinline__ void red4(float4* addr, float4 v) {
    asm volatile("red.global.add.v4.f32 [%0], {%1,%2,%3,%4};"
                 :: "l"(addr), "f"(v.x), "f"(v.y), "f"(v.z), "f"(v.w) : "memory");
}
__device__ __forceinline__ uint32_t smem_u32(const void* p) {
    uint32_t a;
    asm("{ .reg .u64 t; cvta.to.shared.u64 t, %1; cvt.u32.u64 %0, t; }" : "=r"(a) : "l"(p));
    return a;
}

// ---------------- mma / ldmatrix macros (base sm_100 ISA) ----------------
#define MMA_BF16(c, a, b0, b1) \
    asm volatile("mma.sync.aligned.m16n8k16.row.col.f32.bf16.bf16.f32 " \
        "{%0,%1,%2,%3}, {%4,%5,%6,%7}, {%8,%9}, {%0,%1,%2,%3};" \
        : "+f"((c)[0]), "+f"((c)[1]), "+f"((c)[2]), "+f"((c)[3]) \
        : "r"((a)[0]), "r"((a)[1]), "r"((a)[2]), "r"((a)[3]), "r"(b0), "r"(b1))

#define LDSM4(r, addr) \
    asm volatile("ldmatrix.sync.aligned.m8n8.x4.shared.b16 {%0,%1,%2,%3}, [%4];" \
        : "=r"((r)[0]), "=r"((r)[1]), "=r"((r)[2]), "=r"((r)[3]) : "r"(addr))

#define LDSM2(r0, r1, addr) \
    asm volatile("ldmatrix.sync.aligned.m8n8.x2.shared.b16 {%0,%1}, [%2];" \
        : "=r"(r0), "=r"(r1) : "r"(addr))

// smem byte layout
#define SMB_W0HI  0        // 3072 : W0^T [64 n][48B row] bf16 hi (k bytes 0..31)
#define SMB_W0LO  3072     // 3072
#define SMB_B1HI  6144     // 9216 : L1 weights^T [64 n][144B row] bf16 hi
#define SMB_B1LO  15360    // 9216
#define SMB_BHHI  24576    // 18432: head weights^T [128 n][144B row] bf16 hi
#define SMB_BHLO  43008    // 18432
#define SMB_WBUF  61440    // per-warp regions
// per-warp: [0,9216) x hi/lo planes (stride 144), aliased by Cbuf [0,8704)
//           [8704,12928) featw (epilogue phase) | [12928,13440) escal | [13440,13568) sdst
#define WARP_SMEM 13568
#define SM_TOTAL  (61440 + NWARP * WARP_SMEM)   // 224256

// ---------------- kernel A: node linear 1 + zero accumulators ----------------
__global__ void __launch_bounds__(256, 3)
node_pre_kernel(const float* __restrict__ node_s,
                const float* __restrict__ node_v,
                const float* __restrict__ W1sf,
                const float* __restrict__ W1ss,
                const float* __restrict__ W1vf,
                const float* __restrict__ W1vs) {
    __shared__ float sWsf[1024], sWss[1024], sWvf[1024], sWvs[1024];
    for (int i = threadIdx.x; i < 1024; i += blockDim.x) {
        sWsf[i] = W1sf[i]; sWss[i] = W1ss[i];
        sWvf[i] = W1vf[i]; sWvs[i] = W1vs[i];
    }
    __syncthreads();
    int base = blockIdx.x * blockDim.x + threadIdx.x;
    const int STRIDE = 160000;
    const int TOT4 = NNODE * 64;
    for (int i = base; i < TOT4; i += STRIDE) {
        if (i < NNODE * 16) g_ns_mid[i] = make_float4(0.f, 0.f, 0.f, 0.f);
        else                g_nv_mid[i - NNODE * 16] = make_float4(0.f, 0.f, 0.f, 0.f);
    }
    for (int tid = base; tid < NNODE * MUL; tid += STRIDE) {
        int n = tid >> 5, v = tid & 31;
        float afs = 0.f, ass = 0.f;
        float fv0 = 0.f, fv1 = 0.f, fv2 = 0.f;
        float sv0 = 0.f, sv1 = 0.f, sv2 = 0.f;
#pragma unroll 8
        for (int u = 0; u < 32; ++u) {
            float s = node_s[n * 32 + u];
            afs += s * sWsf[u * 32 + v];
            ass += s * sWss[u * 32 + v];
            float c0 = node_v[(n * 32 + u) * 3 + 0];
            float c1 = node_v[(n * 32 + u) * 3 + 1];
            float c2 = node_v[(n * 32 + u) * 3 + 2];
            float wf = sWvf[u * 32 + v];
            float ws = sWvs[u * 32 + v];
            fv0 += c0 * wf; fv1 += c1 * wf; fv2 += c2 * wf;
            sv0 += c0 * ws; sv1 += c1 * ws; sv2 += c2 * ws;
        }
        g_feat[n * 128 + v]            = INV_MUL * afs;
        g_ss[n * 32 + v]               = INV_MUL * ass;
        g_feat[n * 128 + 32 + v]       = INV_MUL * fv0;
        g_feat[n * 128 + 64 + v]       = INV_MUL * fv1;
        g_feat[n * 128 + 96 + v]       = INV_MUL * fv2;
        g_sv[(n * 32 + v) * 3 + 0] = INV_MUL * sv0;
        g_sv[(n * 32 + v) * 3 + 1] = INV_MUL * sv1;
        g_sv[(n * 32 + v) * 3 + 2] = INV_MUL * sv2;
    }
}

// ---------------- kernel B: all-mma edge pipeline + staged scatter ----------------
__global__ void __launch_bounds__(NTHR, 1)
edge_kernel(const float* __restrict__ esa,
            const float* __restrict__ eattr_s,
            const float* __restrict__ eattr_v,
            const int*   __restrict__ e_src,
            const int*   __restrict__ e_dst,
            const float* __restrict__ Wm0,
            const float* __restrict__ Wm1,
            const float* __restrict__ Wi0g,
            const float* __restrict__ Wi1g,
            const float* __restrict__ Wi2g,
            const float* __restrict__ Wi3g) {
    extern __shared__ char smc[];
    const int tid = threadIdx.x;
    const int lane = tid & 31;
    const int wid = tid >> 5;
    uint32_t sbase = smem_u32(smc);

    // ---- stage W0 as bf16 hi/lo B-tiles [64 n][16 k], row stride 48B
    for (int i = tid; i < 1024; i += NTHR) {
        int n = i >> 4, k = i & 15;
        float v = INV_SCAL * Wm0[k * 64 + n];
        __nv_bfloat16 hi = __float2bfloat16(v);
        __nv_bfloat16 lo = __float2bfloat16(v - __bfloat162float(hi));
        *reinterpret_cast<__nv_bfloat16*>(smc + SMB_W0HI + n * 48 + k * 2) = hi;
        *reinterpret_cast<__nv_bfloat16*>(smc + SMB_W0LO + n * 48 + k * 2) = lo;
    }
    // ---- stage L1 weights^T [64 n][64 k], stride 144B, hi/lo
    for (int i = tid; i < 4096; i += NTHR) {
        int n = i >> 6, k = i & 63;
        float v = INV_FC * Wm1[k * 64 + n];
        __nv_bfloat16 hi = __float2bfloat16(v);
        __nv_bfloat16 lo = __float2bfloat16(v - __bfloat162float(hi));
        *reinterpret_cast<__nv_bfloat16*>(smc + SMB_B1HI + n * 144 + k * 2) = hi;
        *reinterpret_cast<__nv_bfloat16*>(smc + SMB_B1LO + n * 144 + k * 2) = lo;
    }
    // ---- stage head weights^T [128 n][64 k], stride 144B, hi/lo
    {
        const float* gW[4] = {Wi0g, Wi1g, Wi2g, Wi3g};
        const float  gS[4] = {INV_FC, INV_FC, INV_FC, INV_FC * INV_SQ3};
        for (int i = tid; i < 8192; i += NTHR) {
            int n = i >> 6, k = i & 63;
            int h = n >> 5, u = n & 31;
            float v = gS[h] * gW[h][k * 32 + u];
            __nv_bfloat16 hi = __float2bfloat16(v);
            __nv_bfloat16 lo = __float2bfloat16(v - __bfloat162float(hi));
            *reinterpret_cast<__nv_bfloat16*>(smc + SMB_BHHI + n * 144 + k * 2) = hi;
            *reinterpret_cast<__nv_bfloat16*>(smc + SMB_BHLO + n * 144 + k * 2) = lo;
        }
    }
    __syncthreads();

    char*  wreg  = smc + SMB_WBUF + wid * WARP_SMEM;
    char*  bufhi = wreg;                              // x hi plane (phase 1)
    char*  buflo = wreg + 4608;                       // x lo plane
    float* CbufF = reinterpret_cast<float*>(wreg);    // C readback 32 x 68 f32 (alias)
    float* featw = reinterpret_cast<float*>(wreg + 8704);    // 8 x 132 f32
    float4* escal = reinterpret_cast<float4*>(wreg + 12928); // 32 x float4
    int*   sdst  = reinterpret_cast<int*>(wreg + 13440);     // 32 x int
    uint32_t a0base = sbase + SMB_WBUF + wid * WARP_SMEM;

    const int idx16 = lane & 15;
    const int brow = idx16 & 7;
    const int bkof = ((idx16 >> 3) & 1) << 4;
    const int role = lane >> 3;
    const int idx  = lane & 7;

    const int NCHUNK = NEDGE / 32;              // 20000
    const int WSTRIDE = 148 * NWARP;

    for (int chunk = blockIdx.x * NWARP + wid; chunk < NCHUNK; chunk += WSTRIDE) {
        int e = chunk * 32 + lane;

        // ---- per-edge metadata early (overlaps compute)
        int src = e_src[e];
        int dst = e_dst[e];
        float eas = eattr_s[e];
        float av0 = eattr_v[3 * e + 0];
        float av1 = eattr_v[3 * e + 1];
        float av2 = eattr_v[3 * e + 2];
        escal[lane] = make_float4(eas, av0, av1, av2);
        sdst[lane] = dst;

        // ---- store radial x (16 floats) as bf16 hi/lo rows (stride 144B)
        const ulonglong2* xq = reinterpret_cast<const ulonglong2*>(esa + (size_t)e * 16);
        ulonglong2 q0 = xq[0], q1 = xq[1], q2 = xq[2], q3 = xq[3];
        u64 xp[8] = {q0.x, q0.y, q1.x, q1.y, q2.x, q2.y, q3.x, q3.y};
#pragma unroll
        for (int i = 0; i < 8; i += 2) {
            float2 p0 = upk2(xp[i]), p1 = upk2(xp[i + 1]);
            __nv_bfloat162 h0a = __float22bfloat162_rn(p0);
            __nv_bfloat162 h0b = __float22bfloat162_rn(p1);
            float2 f0 = __bfloat1622float2(h0a);
            float2 f1 = __bfloat1622float2(h0b);
            __nv_bfloat162 l0a = __float22bfloat162_rn(make_float2(p0.x - f0.x, p0.y - f0.y));
            __nv_bfloat162 l0b = __float22bfloat162_rn(make_float2(p1.x - f1.x, p1.y - f1.y));
            uint32_t ha = *reinterpret_cast<uint32_t*>(&h0a);
            uint32_t hb = *reinterpret_cast<uint32_t*>(&h0b);
            uint32_t la = *reinterpret_cast<uint32_t*>(&l0a);
            uint32_t lb = *reinterpret_cast<uint32_t*>(&l0b);
            *reinterpret_cast<u64*>(bufhi + lane * 144 + i * 4) = ((u64)hb << 32) | ha;
            *reinterpret_cast<u64*>(buflo + lane * 144 + i * 4) = ((u64)lb << 32) | la;
        }
        __syncwarp();

        // ---- A-x fragments (K=16: single k-tile)
        uint32_t Axh[2][4], Axl[2][4];
#pragma unroll
        for (int m = 0; m < 2; ++m) {
            uint32_t addr = a0base
                + (uint32_t)((m * 16 + (lane & 7) + ((lane >> 3) & 1) * 8) * 144)
                + (uint32_t)(((lane >> 4) & 1) * 16);
            LDSM4(Axh[m], addr);
            LDSM4(Axl[m], addr + 4608);
        }
        __syncwarp();

        // ---- L0 mma: C0[32 x 64] = X[32 x 16] * W0^T, 3-pass hi/lo
        float C0[2][8][4];
#pragma unroll
        for (int m = 0; m < 2; ++m)
#pragma unroll
            for (int n = 0; n < 8; ++n)
#pragma unroll
                for (int q = 0; q < 4; ++q) C0[m][n][q] = 0.f;
#pragma unroll
        for (int n = 0; n < 8; ++n) {
            uint32_t baddr = sbase + SMB_W0HI + (uint32_t)((n * 8 + brow) * 48) + bkof;
            uint32_t bh0, bh1, bl0, bl1;
            LDSM2(bh0, bh1, baddr);
            LDSM2(bl0, bl1, baddr + 3072);
#pragma unroll
            for (int m = 0; m < 2; ++m) {
                MMA_BF16(C0[m][n], Axh[m], bh0, bh1);
                MMA_BF16(C0[m][n], Axl[m], bh0, bh1);
                MMA_BF16(C0[m][n], Axh[m], bl0, bl1);
            }
        }

        // ---- gelu in-fragment -> L1 A fragments
        uint32_t A0h[2][4][4], A0l[2][4][4];
#pragma unroll
        for (int m = 0; m < 2; ++m)
#pragma unroll
            for (int k = 0; k < 4; ++k) {
#pragma unroll
                for (int half = 0; half < 2; ++half) {
                    const float* cp = C0[m][2 * k + half];
#pragma unroll
                    for (int pp = 0; pp < 2; ++pp) {
                        float2 p = upk2(gelu2(cp[2 * pp], cp[2 * pp + 1]));
                        __nv_bfloat162 hi2 = __float22bfloat162_rn(p);
                        float2 hf = __bfloat1622float2(hi2);
                        __nv_bfloat162 lo2 =
                            __float22bfloat162_rn(make_float2(p.x - hf.x, p.y - hf.y));
                        A0h[m][k][half * 2 + pp] = *reinterpret_cast<uint32_t*>(&hi2);
                        A0l[m][k][half * 2 + pp] = *reinterpret_cast<uint32_t*>(&lo2);
                    }
                }
            }

        // ---- L1 mma (3-pass hi/lo)
        float C1[2][8][4];
#pragma unroll
        for (int m = 0; m < 2; ++m)
#pragma unroll
            for (int n = 0; n < 8; ++n)
#pragma unroll
                for (int q = 0; q < 4; ++q) C1[m][n][q] = 0.f;
#pragma unroll
        for (int n = 0; n < 8; ++n)
#pragma unroll
            for (int k = 0; k < 4; ++k) {
                uint32_t baddr = sbase + SMB_B1HI
                    + (uint32_t)((n * 8 + brow) * 144) + (uint32_t)(k * 32) + bkof;
                uint32_t bh0, bh1, bl0, bl1;
                LDSM2(bh0, bh1, baddr);
                LDSM2(bl0, bl1, baddr + 9216);
#pragma unroll
                for (int m = 0; m < 2; ++m) {
                    MMA_BF16(C1[m][n], A0h[m][k], bh0, bh1);
                    MMA_BF16(C1[m][n], A0l[m][k], bh0, bh1);
                    MMA_BF16(C1[m][n], A0h[m][k], bl0, bl1);
                }
            }

        // ---- gelu in-fragment -> heads A fragments
        uint32_t A1h[2][4][4], A1l[2][4][4];
#pragma unroll
        for (int m = 0; m < 2; ++m)
#pragma unroll
            for (int k = 0; k < 4; ++k) {
#pragma unroll
                for (int half = 0; half < 2; ++half) {
                    const float* cp = C1[m][2 * k + half];
#pragma unroll
                    for (int pp = 0; pp < 2; ++pp) {
                        float2 p = upk2(gelu2(cp[2 * pp], cp[2 * pp + 1]));
                        __nv_bfloat162 hi2 = __float22bfloat162_rn(p);
                        float2 hf = __bfloat1622float2(hi2);
                        __nv_bfloat162 lo2 =
                            __float22bfloat162_rn(make_float2(p.x - hf.x, p.y - hf.y));
                        A1h[m][k][half * 2 + pp] = *reinterpret_cast<uint32_t*>(&hi2);
                        A1l[m][k][half * 2 + pp] = *reinterpret_cast<uint32_t*>(&lo2);
                    }
                }
            }

        // ---- heads in two 64-col chunks, staged transposed epilogue (R7)
#pragma unroll
        for (int nh = 0; nh < 2; ++nh) {
            float C[2][8][4];
#pragma unroll
            for (int m = 0; m < 2; ++m)
#pragma unroll
                for (int n = 0; n < 8; ++n)
#pragma unroll
                    for (int q = 0; q < 4; ++q) C[m][n][q] = 0.f;
#pragma unroll
            for (int n = 0; n < 8; ++n)
#pragma unroll
                for (int k = 0; k < 4; ++k) {
                    uint32_t baddr = sbase + SMB_BHHI
                        + (uint32_t)(((nh * 8 + n) * 8 + brow) * 144)
                        + (uint32_t)(k * 32) + bkof;
                    uint32_t bh0, bh1, bl0, bl1;
                    LDSM2(bh0, bh1, baddr);
                    LDSM2(bl0, bl1, baddr + 18432);
#pragma unroll
                    for (int m = 0; m < 2; ++m) {
                        MMA_BF16(C[m][n], A1h[m][k], bh0, bh1);
                        MMA_BF16(C[m][n], A1l[m][k], bh0, bh1);
                        MMA_BF16(C[m][n], A1h[m][k], bl0, bl1);
                    }
                }
            // C -> Cbuf (stride 68 floats)
            __syncwarp();
#pragma unroll
            for (int m = 0; m < 2; ++m)
#pragma unroll
                for (int n = 0; n < 8; ++n) {
                    int row = m * 16 + (lane >> 2);
                    int col = n * 8 + 2 * (lane & 3);
                    *reinterpret_cast<float2*>(CbufF + row * 68 + col) =
                        make_float2(C[m][n][0], C[m][n][1]);
                    *reinterpret_cast<float2*>(CbufF + (row + 8) * 68 + col) =
                        make_float2(C[m][n][2], C[m][n][3]);
                }
            __syncwarp();

            // epilogue in 4 subgroups of 8 edges (staged gather)
#pragma unroll
            for (int sub = 0; sub < 4; ++sub) {
                if (nh == 0) {
#pragma unroll
                    for (int m = 0; m < 2; ++m) {
                        int jj = 4 * m + (lane >> 3);
                        int sj = __shfl_sync(0xffffffffu, src, sub * 8 + jj);
                        float4 v = *reinterpret_cast<const float4*>(
                            g_feat + (size_t)sj * 128 + (lane & 7) * 4);
                        *reinterpret_cast<float4*>(featw + jj * 132 + (lane & 7) * 4) = v;
                    }
                } else {
#pragma unroll
                    for (int m = 0; m < 8; ++m) {
                        int sj = __shfl_sync(0xffffffffu, src, sub * 8 + m);
                        if (lane < 24) {
                            float4 v = *reinterpret_cast<const float4*>(
                                g_feat + (size_t)sj * 128 + 32 + lane * 4);
                            *reinterpret_cast<float4*>(featw + m * 132 + 32 + lane * 4) = v;
                        }
                    }
                }
                __syncwarp();

#pragma unroll
                for (int jj = 0; jj < 8; ++jj) {
                    int j = sub * 8 + jj;
                    float4 sc = escal[j];
                    int dstj = sdst[j];
                    float4 o;
                    float4* addr;
                    if (nh == 0) {
                        float4 wch = *reinterpret_cast<const float4*>(
                            CbufF + j * 68 + (role == 0 ? 0 : 32) + idx * 4);
                        float4 esc = *reinterpret_cast<const float4*>(
                            featw + jj * 132 + idx * 4);
                        float s = (role == 0) ? sc.x :
                                  (role == 1) ? sc.y : (role == 2) ? sc.z : sc.w;
                        o.x = wch.x * esc.x * s; o.y = wch.y * esc.y * s;
                        o.z = wch.z * esc.z * s; o.w = wch.w * esc.w * s;
                        addr = (role == 0) ? (g_ns_mid + dstj * 16 + idx)
                             : (g_nv_mid + dstj * 48 + (role - 1) * 16 + idx);
                    } else {
                        if (role < 3) {
                            float4 w2 = *reinterpret_cast<const float4*>(
                                CbufF + j * 68 + idx * 4);
                            float4 ev = *reinterpret_cast<const float4*>(
                                featw + jj * 132 + 32 + role * 32 + idx * 4);
                            o.x = w2.x * ev.x * sc.x; o.y = w2.y * ev.y * sc.x;
                            o.z = w2.z * ev.z * sc.x; o.w = w2.w * ev.w * sc.x;
                            addr = g_nv_mid + dstj * 48 + role * 16 + 8 + idx;
                        } else {
                            float4 w3 = *reinterpret_cast<const float4*>(
                                CbufF + j * 68 + 32 + idx * 4);
                            float4 e0 = *reinterpret_cast<const float4*>(
                                featw + jj * 132 + 32 + idx * 4);
                            float4 e1 = *reinterpret_cast<const float4*>(
                                featw + jj * 132 + 64 + idx * 4);
                            float4 e2 = *reinterpret_cast<const float4*>(
                                featw + jj * 132 + 96 + idx * 4);
                            float4 d;
                            d.x = e0.x * sc.y + e1.x * sc.z + e2.x * sc.w;
                            d.y = e0.y * sc.y + e1.y * sc.z + e2.y * sc.w;
                            d.z = e0.z * sc.y + e1.z * sc.z + e2.z * sc.w;
                            d.w = e0.w * sc.y + e1.w * sc.z + e2.w * sc.w;
                            o.x = w3.x * d.x; o.y = w3.y * d.y;
                            o.z = w3.z * d.z; o.w = w3.w * d.w;
                            addr = g_ns_mid + dstj * 16 + 8 + idx;
                        }
                    }
                    red4(addr, o);
                }
                __syncwarp();
            }
        }
        __syncwarp();
    }
}

// ---------------- kernel C: node linear 2 + mix ----------------
__global__ void __launch_bounds__(256, 3)
node_post_kernel(const float* __restrict__ W2s,
                 const float* __restrict__ W2v,
                 float* __restrict__ out) {
    __shared__ float sW2s[2048], sW2v[2048];
    for (int i = threadIdx.x; i < 2048; i += blockDim.x) {
        sW2s[i] = W2s[i]; sW2v[i] = W2v[i];
    }
    __syncthreads();
    int base = blockIdx.x * blockDim.x + threadIdx.x;
    const int STRIDE = 160000;
    for (int tid = base; tid < NNODE * MUL; tid += STRIDE) {
        int n = tid >> 5, v = tid & 31;
        const float* ms = reinterpret_cast<const float*>(g_ns_mid) + n * 64;
        const float* mv = reinterpret_cast<const float*>(g_nv_mid) + n * 192;
        float cs = 0.f, cv0 = 0.f, cv1 = 0.f, cv2 = 0.f;
#pragma unroll 8
        for (int u = 0; u < 64; ++u) {
            float ws = sW2s[u * 32 + v];
            float wv = sW2v[u * 32 + v];
            cs  += ms[u] * ws;
            cv0 += mv[u]       * wv;
            cv1 += mv[64 + u]  * wv;
            cv2 += mv[128 + u] * wv;
        }
        const float SC = SIN_A * INV_MID * INV_NB;
        out[n * 32 + v] = COS_A * g_ss[n * 32 + v] + SC * cs;
        float* outv = out + NNODE * 32;
        int b = (n * 32 + v) * 3;
        outv[b + 0] = COS_A * g_sv[b + 0] + SC * cv0;
        outv[b + 1] = COS_A * g_sv[b + 1] + SC * cv1;
        outv[b + 2] = COS_A * g_sv[b + 2] + SC * cv2;
    }
}

// ---------------- launch ----------------
extern "C" void kernel_launch(void* const* d_in, const int* in_sizes, int n_in,
                              void* d_out, int out_size) {
    const float *node_s, *node_v, *eattr_s, *eattr_v, *esa;
    const float *W1sf, *W1ss, *W1vf, *W1vs, *Wm0, *Wm1;
    const float *Wi0, *Wi1, *Wi2, *Wi3, *W2s, *W2v;
    const int *e_src, *e_dst;

    node_s  = (const float*)d_in[0];
    node_v  = (const float*)d_in[1];
    eattr_s = (const float*)d_in[2];
    eattr_v = (const float*)d_in[3];
    esa     = (const float*)d_in[4];
    if (in_sizes[5] == NEDGE) {
        e_src = (const int*)d_in[5];
        e_dst = (const int*)d_in[6];
        W1sf = (const float*)d_in[7];  W1ss = (const float*)d_in[8];
        W1vf = (const float*)d_in[9];  W1vs = (const float*)d_in[10];
        Wm0  = (const float*)d_in[11]; Wm1  = (const float*)d_in[12];
        Wi0  = (const float*)d_in[13]; Wi1  = (const float*)d_in[14];
        Wi2  = (const float*)d_in[15]; Wi3  = (const float*)d_in[16];
        W2s  = (const float*)d_in[17]; W2v  = (const float*)d_in[18];
    } else {
        W1sf = (const float*)d_in[5];  W1ss = (const float*)d_in[6];
        W1vf = (const float*)d_in[7];  W1vs = (const float*)d_in[8];
        Wm0  = (const float*)d_in[9];  Wm1  = (const float*)d_in[10];
        Wi0  = (const float*)d_in[11]; Wi1  = (const float*)d_in[12];
        Wi2  = (const float*)d_in[13]; Wi3  = (const float*)d_in[14];
        W2s  = (const float*)d_in[15]; W2v  = (const float*)d_in[16];
        e_src = (const int*)d_in[17];
        e_dst = (const int*)d_in[18];
    }

    cudaFuncSetAttribute(edge_kernel,
                         cudaFuncAttributeMaxDynamicSharedMemorySize, SM_TOTAL);

    node_pre_kernel<<<625, 256>>>(node_s, node_v, W1sf, W1ss, W1vf, W1vs);

    edge_kernel<<<148, NTHR, SM_TOTAL>>>(
        esa, eattr_s, eattr_v, e_src, e_dst, Wm0, Wm1, Wi0, Wi1, Wi2, Wi3);

    node_post_kernel<<<625, 256>>>(W2s, W2v, (float*)d_out);
}

// round 12
// speedup vs baseline: 1.2573x; 1.0389x over previous
#include <cuda_runtime.h>
#include <cuda_bf16.h>
#include <math.h>
#include <stdint.h>

#define NNODE 20000
#define NEDGE 640000
#define MUL 32
#define FC 64
#define SCAL 16

#define INV_MUL  0.17677669529663687f
#define INV_FC   0.125f
#define INV_SCAL 0.25f
#define INV_SQ3  0.57735026918962576f
#define COS_A    0.92387953251128674f
#define SIN_A    0.38268343236508978f
#define INV_NB   0.17677669529663687f
#define INV_MID  0.125f

#define NWARP 12
#define NTHR  (NWARP * 32)

typedef unsigned long long u64;

// ---------------- device scratch ----------------
__device__ float  g_feat[NNODE * 128];      // [N]: [0..32)=fs, [32+c*32+u]=fv
__device__ float  g_ss[NNODE * MUL];
__device__ float  g_sv[NNODE * MUL * 3];    // [N][32][3]
__device__ float4 g_ns_mid[NNODE * 16];     // [N][64]
__device__ float4 g_nv_mid[NNODE * 48];     // [N][3][64]

// ---------------- packed f32x2 helpers ----------------
__device__ __forceinline__ u64 pk2(float lo, float hi) {
    u64 r; asm("mov.b64 %0,{%1,%2};" : "=l"(r) : "f"(lo), "f"(hi)); return r;
}
__device__ __forceinline__ float2 upk2(u64 v) {
    float2 f; asm("mov.b64 {%0,%1},%2;" : "=f"(f.x), "=f"(f.y) : "l"(v)); return f;
}
__device__ __forceinline__ u64 f2fma(u64 a, u64 b, u64 c) {
    u64 d; asm("fma.rn.f32x2 %0,%1,%2,%3;" : "=l"(d) : "l"(a), "l"(b), "l"(c)); return d;
}
__device__ __forceinline__ u64 f2mul(u64 a, u64 b) {
    u64 d; asm("mul.rn.f32x2 %0,%1,%2;" : "=l"(d) : "l"(a), "l"(b)); return d;
}
__device__ __forceinline__ u64 f2add(u64 a, u64 b) {
    u64 d; asm("add.rn.f32x2 %0,%1,%2;" : "=l"(d) : "l"(a), "l"(b)); return d;
}
__device__ __forceinline__ float tanh_ap(float x) {
    float y; asm("tanh.approx.f32 %0,%1;" : "=f"(y) : "f"(x)); return y;
}
__device__ __forceinline__ u64 gelu2(float s0, float s1) {
    const u64 C1D = pk2(0.79788456080286535588f, 0.79788456080286535588f);
    const u64 C2D = pk2(0.03567740813636141f, 0.03567740813636141f);
    u64 x = pk2(s0, s1);
    u64 x2 = f2mul(x, x);
    u64 arg = f2mul(x, f2fma(x2, C2D, C1D));
    float2 a = upk2(arg);
    u64 tp = pk2(tanh_ap(a.x), tanh_ap(a.y));
    return f2mul(f2mul(x, pk2(0.5f, 0.5f)), f2add(pk2(1.f, 1.f), tp));
}
__device__ __forceinline__ void red4(float4* addr, float4 v) {
    asm volatile("red.global.add.v4.f32 [%0], {%1,%2,%3,%4};"
                 :: "l"(addr), "f"(v.x), "f"(v.y), "f"(v.z), "f"(v.w) : "memory");
}
__device__ __forceinline__ uint32_t smem_u32(const void* p) {
    uint32_t a;
    asm("{ .reg .u64 t; cvta.to.shared.u64 t, %1; cvt.u32.u64 %0, t; }" : "=r"(a) : "l"(p));
    return a;
}

// ---------------- mma / ldmatrix macros (base sm_100 ISA) ----------------
#define MMA_BF16(c, a, b0, b1) \
    asm volatile("mma.sync.aligned.m16n8k16.row.col.f32.bf16.bf16.f32 " \
        "{%0,%1,%2,%3}, {%4,%5,%6,%7}, {%8,%9}, {%0,%1,%2,%3};" \
        : "+f"((c)[0]), "+f"((c)[1]), "+f"((c)[2]), "+f"((c)[3]) \
        : "r"((a)[0]), "r"((a)[1]), "r"((a)[2]), "r"((a)[3]), "r"(b0), "r"(b1))

#define LDSM4(r, addr) \
    asm volatile("ldmatrix.sync.aligned.m8n8.x4.shared.b16 {%0,%1,%2,%3}, [%4];" \
        : "=r"((r)[0]), "=r"((r)[1]), "=r"((r)[2]), "=r"((r)[3]) : "r"(addr))

#define LDSM2(r0, r1, addr) \
    asm volatile("ldmatrix.sync.aligned.m8n8.x2.shared.b16 {%0,%1}, [%2];" \
        : "=r"(r0), "=r"(r1) : "r"(addr))

// smem byte layout (edge kernel)
#define SMB_W0HI  0        // 3072 : W0^T [64 n][48B row] bf16 hi
#define SMB_W0LO  3072     // 3072
#define SMB_B1HI  6144     // 9216 : L1 weights^T [64 n][144B row] bf16 hi
#define SMB_B1LO  15360    // 9216
#define SMB_BHHI  24576    // 18432: head weights^T [128 n][144B row] bf16 hi
#define SMB_BHLO  43008    // 18432
#define SMB_WBUF  61440    // per-warp regions
#define WARP_SMEM 13568
#define SM_TOTAL  (61440 + NWARP * WARP_SMEM)   // 224256

// ---------------- kernel A: node linear 1 (smem-staged) + zero accumulators ----------------
__global__ void __launch_bounds__(256, 3)
node_pre_kernel(const float* __restrict__ node_s,
                const float* __restrict__ node_v,
                const float* __restrict__ W1sf,
                const float* __restrict__ W1ss,
                const float* __restrict__ W1vf,
                const float* __restrict__ W1vs) {
    __shared__ float sWsf[1024], sWss[1024], sWvf[1024], sWvs[1024];
    __shared__ float sS[256];    // 8 nodes x 32 scalars
    __shared__ float sV[768];    // 8 nodes x 96 vector comps
    int tid = threadIdx.x;
    for (int i = tid; i < 1024; i += 256) {
        sWsf[i] = W1sf[i]; sWss[i] = W1ss[i];
        sWvf[i] = W1vf[i]; sWvs[i] = W1vs[i];
    }
    // zero mid accumulators (grid-stride)
    int base = blockIdx.x * blockDim.x + tid;
    const int STRIDE = 160000;
    const int TOT4 = NNODE * 64;
    for (int i = base; i < TOT4; i += STRIDE) {
        if (i < NNODE * 16) g_ns_mid[i] = make_float4(0.f, 0.f, 0.f, 0.f);
        else                g_nv_mid[i - NNODE * 16] = make_float4(0.f, 0.f, 0.f, 0.f);
    }
    __syncthreads();

    int nl = tid >> 5, v = tid & 31;
    for (int g = blockIdx.x; g < NNODE / 8; g += gridDim.x) {
        int ng = g * 8;
        // coalesced stage: node_s 64 float4, node_v 192 float4
        if (tid < 64)
            reinterpret_cast<float4*>(sS)[tid] =
                reinterpret_cast<const float4*>(node_s + (size_t)ng * 32)[tid];
        else
            reinterpret_cast<float4*>(sV)[tid - 64] =
                reinterpret_cast<const float4*>(node_v + (size_t)ng * 96)[tid - 64];
        __syncthreads();

        int n = ng + nl;
        const float* pS = sS + nl * 32;
        const float* pV = sV + nl * 96;
        float afs = 0.f, ass = 0.f;
        float fv0 = 0.f, fv1 = 0.f, fv2 = 0.f;
        float sv0 = 0.f, sv1 = 0.f, sv2 = 0.f;
#pragma unroll 8
        for (int u = 0; u < 32; ++u) {
            float s = pS[u];
            afs += s * sWsf[u * 32 + v];
            ass += s * sWss[u * 32 + v];
            float c0 = pV[u * 3 + 0];
            float c1 = pV[u * 3 + 1];
            float c2 = pV[u * 3 + 2];
            float wf = sWvf[u * 32 + v];
            float ws = sWvs[u * 32 + v];
            fv0 += c0 * wf; fv1 += c1 * wf; fv2 += c2 * wf;
            sv0 += c0 * ws; sv1 += c1 * ws; sv2 += c2 * ws;
        }
        g_feat[n * 128 + v]      = INV_MUL * afs;
        g_ss[n * 32 + v]         = INV_MUL * ass;
        g_feat[n * 128 + 32 + v] = INV_MUL * fv0;
        g_feat[n * 128 + 64 + v] = INV_MUL * fv1;
        g_feat[n * 128 + 96 + v] = INV_MUL * fv2;
        g_sv[(n * 32 + v) * 3 + 0] = INV_MUL * sv0;
        g_sv[(n * 32 + v) * 3 + 1] = INV_MUL * sv1;
        g_sv[(n * 32 + v) * 3 + 2] = INV_MUL * sv2;
        __syncthreads();
    }
}

// ---------------- kernel B: all-mma edge pipeline + staged scatter (R11, unchanged) ----------------
__global__ void __launch_bounds__(NTHR, 1)
edge_kernel(const float* __restrict__ esa,
            const float* __restrict__ eattr_s,
            const float* __restrict__ eattr_v,
            const int*   __restrict__ e_src,
            const int*   __restrict__ e_dst,
            const float* __restrict__ Wm0,
            const float* __restrict__ Wm1,
            const float* __restrict__ Wi0g,
            const float* __restrict__ Wi1g,
            const float* __restrict__ Wi2g,
            const float* __restrict__ Wi3g) {
    extern __shared__ char smc[];
    const int tid = threadIdx.x;
    const int lane = tid & 31;
    const int wid = tid >> 5;
    uint32_t sbase = smem_u32(smc);

    for (int i = tid; i < 1024; i += NTHR) {
        int n = i >> 4, k = i & 15;
        float v = INV_SCAL * Wm0[k * 64 + n];
        __nv_bfloat16 hi = __float2bfloat16(v);
        __nv_bfloat16 lo = __float2bfloat16(v - __bfloat162float(hi));
        *reinterpret_cast<__nv_bfloat16*>(smc + SMB_W0HI + n * 48 + k * 2) = hi;
        *reinterpret_cast<__nv_bfloat16*>(smc + SMB_W0LO + n * 48 + k * 2) = lo;
    }
    for (int i = tid; i < 4096; i += NTHR) {
        int n = i >> 6, k = i & 63;
        float v = INV_FC * Wm1[k * 64 + n];
        __nv_bfloat16 hi = __float2bfloat16(v);
        __nv_bfloat16 lo = __float2bfloat16(v - __bfloat162float(hi));
        *reinterpret_cast<__nv_bfloat16*>(smc + SMB_B1HI + n * 144 + k * 2) = hi;
        *reinterpret_cast<__nv_bfloat16*>(smc + SMB_B1LO + n * 144 + k * 2) = lo;
    }
    {
        const float* gW[4] = {Wi0g, Wi1g, Wi2g, Wi3g};
        const float  gS[4] = {INV_FC, INV_FC, INV_FC, INV_FC * INV_SQ3};
        for (int i = tid; i < 8192; i += NTHR) {
            int n = i >> 6, k = i & 63;
            int h = n >> 5, u = n & 31;
            float v = gS[h] * gW[h][k * 32 + u];
            __nv_bfloat16 hi = __float2bfloat16(v);
            __nv_bfloat16 lo = __float2bfloat16(v - __bfloat162float(hi));
            *reinterpret_cast<__nv_bfloat16*>(smc + SMB_BHHI + n * 144 + k * 2) = hi;
            *reinterpret_cast<__nv_bfloat16*>(smc + SMB_BHLO + n * 144 + k * 2) = lo;
        }
    }
    __syncthreads();

    char*  wreg  = smc + SMB_WBUF + wid * WARP_SMEM;
    char*  bufhi = wreg;
    char*  buflo = wreg + 4608;
    float* CbufF = reinterpret_cast<float*>(wreg);
    float* featw = reinterpret_cast<float*>(wreg + 8704);
    float4* escal = reinterpret_cast<float4*>(wreg + 12928);
    int*   sdst  = reinterpret_cast<int*>(wreg + 13440);
    uint32_t a0base = sbase + SMB_WBUF + wid * WARP_SMEM;

    const int idx16 = lane & 15;
    const int brow = idx16 & 7;
    const int bkof = ((idx16 >> 3) & 1) << 4;
    const int role = lane >> 3;
    const int idx  = lane & 7;

    const int NCHUNK = NEDGE / 32;
    const int WSTRIDE = 148 * NWARP;

    for (int chunk = blockIdx.x * NWARP + wid; chunk < NCHUNK; chunk += WSTRIDE) {
        int e = chunk * 32 + lane;

        int src = e_src[e];
        int dst = e_dst[e];
        float eas = eattr_s[e];
        float av0 = eattr_v[3 * e + 0];
        float av1 = eattr_v[3 * e + 1];
        float av2 = eattr_v[3 * e + 2];
        escal[lane] = make_float4(eas, av0, av1, av2);
        sdst[lane] = dst;

        const ulonglong2* xq = reinterpret_cast<const ulonglong2*>(esa + (size_t)e * 16);
        ulonglong2 q0 = xq[0], q1 = xq[1], q2 = xq[2], q3 = xq[3];
        u64 xp[8] = {q0.x, q0.y, q1.x, q1.y, q2.x, q2.y, q3.x, q3.y};
#pragma unroll
        for (int i = 0; i < 8; i += 2) {
            float2 p0 = upk2(xp[i]), p1 = upk2(xp[i + 1]);
            __nv_bfloat162 h0a = __float22bfloat162_rn(p0);
            __nv_bfloat162 h0b = __float22bfloat162_rn(p1);
            float2 f0 = __bfloat1622float2(h0a);
            float2 f1 = __bfloat1622float2(h0b);
            __nv_bfloat162 l0a = __float22bfloat162_rn(make_float2(p0.x - f0.x, p0.y - f0.y));
            __nv_bfloat162 l0b = __float22bfloat162_rn(make_float2(p1.x - f1.x, p1.y - f1.y));
            uint32_t ha = *reinterpret_cast<uint32_t*>(&h0a);
            uint32_t hb = *reinterpret_cast<uint32_t*>(&h0b);
            uint32_t la = *reinterpret_cast<uint32_t*>(&l0a);
            uint32_t lb = *reinterpret_cast<uint32_t*>(&l0b);
            *reinterpret_cast<u64*>(bufhi + lane * 144 + i * 4) = ((u64)hb << 32) | ha;
            *reinterpret_cast<u64*>(buflo + lane * 144 + i * 4) = ((u64)lb << 32) | la;
        }
        __syncwarp();

        uint32_t Axh[2][4], Axl[2][4];
#pragma unroll
        for (int m = 0; m < 2; ++m) {
            uint32_t addr = a0base
                + (uint32_t)((m * 16 + (lane & 7) + ((lane >> 3) & 1) * 8) * 144)
                + (uint32_t)(((lane >> 4) & 1) * 16);
            LDSM4(Axh[m], addr);
            LDSM4(Axl[m], addr + 4608);
        }
        __syncwarp();

        float C0[2][8][4];
#pragma unroll
        for (int m = 0; m < 2; ++m)
#pragma unroll
            for (int n = 0; n < 8; ++n)
#pragma unroll
                for (int q = 0; q < 4; ++q) C0[m][n][q] = 0.f;
#pragma unroll
        for (int n = 0; n < 8; ++n) {
            uint32_t baddr = sbase + SMB_W0HI + (uint32_t)((n * 8 + brow) * 48) + bkof;
            uint32_t bh0, bh1, bl0, bl1;
            LDSM2(bh0, bh1, baddr);
            LDSM2(bl0, bl1, baddr + 3072);
#pragma unroll
            for (int m = 0; m < 2; ++m) {
                MMA_BF16(C0[m][n], Axh[m], bh0, bh1);
                MMA_BF16(C0[m][n], Axl[m], bh0, bh1);
                MMA_BF16(C0[m][n], Axh[m], bl0, bl1);
            }
        }

        uint32_t A0h[2][4][4], A0l[2][4][4];
#pragma unroll
        for (int m = 0; m < 2; ++m)
#pragma unroll
            for (int k = 0; k < 4; ++k) {
#pragma unroll
                for (int half = 0; half < 2; ++half) {
                    const float* cp = C0[m][2 * k + half];
#pragma unroll
                    for (int pp = 0; pp < 2; ++pp) {
                        float2 p = upk2(gelu2(cp[2 * pp], cp[2 * pp + 1]));
                        __nv_bfloat162 hi2 = __float22bfloat162_rn(p);
                        float2 hf = __bfloat1622float2(hi2);
                        __nv_bfloat162 lo2 =
                            __float22bfloat162_rn(make_float2(p.x - hf.x, p.y - hf.y));
                        A0h[m][k][half * 2 + pp] = *reinterpret_cast<uint32_t*>(&hi2);
                        A0l[m][k][half * 2 + pp] = *reinterpret_cast<uint32_t*>(&lo2);
                    }
                }
            }

        float C1[2][8][4];
#pragma unroll
        for (int m = 0; m < 2; ++m)
#pragma unroll
            for (int n = 0; n < 8; ++n)
#pragma unroll
                for (int q = 0; q < 4; ++q) C1[m][n][q] = 0.f;
#pragma unroll
        for (int n = 0; n < 8; ++n)
#pragma unroll
            for (int k = 0; k < 4; ++k) {
                uint32_t baddr = sbase + SMB_B1HI
                    + (uint32_t)((n * 8 + brow) * 144) + (uint32_t)(k * 32) + bkof;
                uint32_t bh0, bh1, bl0, bl1;
                LDSM2(bh0, bh1, baddr);
                LDSM2(bl0, bl1, baddr + 9216);
#pragma unroll
                for (int m = 0; m < 2; ++m) {
                    MMA_BF16(C1[m][n], A0h[m][k], bh0, bh1);
                    MMA_BF16(C1[m][n], A0l[m][k], bh0, bh1);
                    MMA_BF16(C1[m][n], A0h[m][k], bl0, bl1);
                }
            }

        uint32_t A1h[2][4][4], A1l[2][4][4];
#pragma unroll
        for (int m = 0; m < 2; ++m)
#pragma unroll
            for (int k = 0; k < 4; ++k) {
#pragma unroll
                for (int half = 0; half < 2; ++half) {
                    const float* cp = C1[m][2 * k + half];
#pragma unroll
                    for (int pp = 0; pp < 2; ++pp) {
                        float2 p = upk2(gelu2(cp[2 * pp], cp[2 * pp + 1]));
                        __nv_bfloat162 hi2 = __float22bfloat162_rn(p);
                        float2 hf = __bfloat1622float2(hi2);
                        __nv_bfloat162 lo2 =
                            __float22bfloat162_rn(make_float2(p.x - hf.x, p.y - hf.y));
                        A1h[m][k][half * 2 + pp] = *reinterpret_cast<uint32_t*>(&hi2);
                        A1l[m][k][half * 2 + pp] = *reinterpret_cast<uint32_t*>(&lo2);
                    }
                }
            }

#pragma unroll
        for (int nh = 0; nh < 2; ++nh) {
            float C[2][8][4];
#pragma unroll
            for (int m = 0; m < 2; ++m)
#pragma unroll
                for (int n = 0; n < 8; ++n)
#pragma unroll
                    for (int q = 0; q < 4; ++q) C[m][n][q] = 0.f;
#pragma unroll
            for (int n = 0; n < 8; ++n)
#pragma unroll
                for (int k = 0; k < 4; ++k) {
                    uint32_t baddr = sbase + SMB_BHHI
                        + (uint32_t)(((nh * 8 + n) * 8 + brow) * 144)
                        + (uint32_t)(k * 32) + bkof;
                    uint32_t bh0, bh1, bl0, bl1;
                    LDSM2(bh0, bh1, baddr);
                    LDSM2(bl0, bl1, baddr + 18432);
#pragma unroll
                    for (int m = 0; m < 2; ++m) {
                        MMA_BF16(C[m][n], A1h[m][k], bh0, bh1);
                        MMA_BF16(C[m][n], A1l[m][k], bh0, bh1);
                        MMA_BF16(C[m][n], A1h[m][k], bl0, bl1);
                    }
                }
            __syncwarp();
#pragma unroll
            for (int m = 0; m < 2; ++m)
#pragma unroll
                for (int n = 0; n < 8; ++n) {
                    int row = m * 16 + (lane >> 2);
                    int col = n * 8 + 2 * (lane & 3);
                    *reinterpret_cast<float2*>(CbufF + row * 68 + col) =
                        make_float2(C[m][n][0], C[m][n][1]);
                    *reinterpret_cast<float2*>(CbufF + (row + 8) * 68 + col) =
                        make_float2(C[m][n][2], C[m][n][3]);
                }
            __syncwarp();

#pragma unroll
            for (int sub = 0; sub < 4; ++sub) {
                if (nh == 0) {
#pragma unroll
                    for (int m = 0; m < 2; ++m) {
                        int jj = 4 * m + (lane >> 3);
                        int sj = __shfl_sync(0xffffffffu, src, sub * 8 + jj);
                        float4 v = *reinterpret_cast<const float4*>(
                            g_feat + (size_t)sj * 128 + (lane & 7) * 4);
                        *reinterpret_cast<float4*>(featw + jj * 132 + (lane & 7) * 4) = v;
                    }
                } else {
#pragma unroll
                    for (int m = 0; m < 8; ++m) {
                        int sj = __shfl_sync(0xffffffffu, src, sub * 8 + m);
                        if (lane < 24) {
                            float4 v = *reinterpret_cast<const float4*>(
                                g_feat + (size_t)sj * 128 + 32 + lane * 4);
                            *reinterpret_cast<float4*>(featw + m * 132 + 32 + lane * 4) = v;
                        }
                    }
                }
                __syncwarp();

#pragma unroll
                for (int jj = 0; jj < 8; ++jj) {
                    int j = sub * 8 + jj;
                    float4 sc = escal[j];
                    int dstj = sdst[j];
                    float4 o;
                    float4* addr;
                    if (nh == 0) {
                        float4 wch = *reinterpret_cast<const float4*>(
                            CbufF + j * 68 + (role == 0 ? 0 : 32) + idx * 4);
                        float4 esc = *reinterpret_cast<const float4*>(
                            featw + jj * 132 + idx * 4);
                        float s = (role == 0) ? sc.x :
                                  (role == 1) ? sc.y : (role == 2) ? sc.z : sc.w;
                        o.x = wch.x * esc.x * s; o.y = wch.y * esc.y * s;
                        o.z = wch.z * esc.z * s; o.w = wch.w * esc.w * s;
                        addr = (role == 0) ? (g_ns_mid + dstj * 16 + idx)
                             : (g_nv_mid + dstj * 48 + (role - 1) * 16 + idx);
                    } else {
                        if (role < 3) {
                            float4 w2 = *reinterpret_cast<const float4*>(
                                CbufF + j * 68 + idx * 4);
                            float4 ev = *reinterpret_cast<const float4*>(
                                featw + jj * 132 + 32 + role * 32 + idx * 4);
                            o.x = w2.x * ev.x * sc.x; o.y = w2.y * ev.y * sc.x;
                            o.z = w2.z * ev.z * sc.x; o.w = w2.w * ev.w * sc.x;
                            addr = g_nv_mid + dstj * 48 + role * 16 + 8 + idx;
                        } else {
                            float4 w3 = *reinterpret_cast<const float4*>(
                                CbufF + j * 68 + 32 + idx * 4);
                            float4 e0 = *reinterpret_cast<const float4*>(
                                featw + jj * 132 + 32 + idx * 4);
                            float4 e1 = *reinterpret_cast<const float4*>(
                                featw + jj * 132 + 64 + idx * 4);
                            float4 e2 = *reinterpret_cast<const float4*>(
                                featw + jj * 132 + 96 + idx * 4);
                            float4 d;
                            d.x = e0.x * sc.y + e1.x * sc.z + e2.x * sc.w;
                            d.y = e0.y * sc.y + e1.y * sc.z + e2.y * sc.w;
                            d.z = e0.z * sc.y + e1.z * sc.z + e2.z * sc.w;
                            d.w = e0.w * sc.y + e1.w * sc.z + e2.w * sc.w;
                            o.x = w3.x * d.x; o.y = w3.y * d.y;
                            o.z = w3.z * d.z; o.w = w3.w * d.w;
                            addr = g_ns_mid + dstj * 16 + 8 + idx;
                        }
                    }
                    red4(addr, o);
                }
                __syncwarp();
            }
        }
        __syncwarp();
    }
}

// ---------------- kernel C: node linear 2 (smem-staged) + mix ----------------
__global__ void __launch_bounds__(256, 3)
node_post_kernel(const float* __restrict__ W2s,
                 const float* __restrict__ W2v,
                 float* __restrict__ out) {
    __shared__ float sW2s[2048], sW2v[2048];
    __shared__ float sMid[8 * 256];   // 8 nodes x (64 ms + 192 mv)
    int tid = threadIdx.x;
    for (int i = tid; i < 2048; i += 256) {
        sW2s[i] = W2s[i]; sW2v[i] = W2v[i];
    }
    __syncthreads();

    int nl = tid >> 5, v = tid & 31;
    for (int g = blockIdx.x; g < NNODE / 8; g += gridDim.x) {
        int ng = g * 8;
        // coalesced stage: per node 16 float4 (ns_mid) + 48 float4 (nv_mid)
#pragma unroll
        for (int q = 0; q < 2; ++q) {
            int i = q * 256 + tid;            // 0..511
            int nn = i >> 6, off = i & 63;
            float4 val = (off < 16) ? g_ns_mid[(ng + nn) * 16 + off]
                                    : g_nv_mid[(ng + nn) * 48 + (off - 16)];
            reinterpret_cast<float4*>(sMid)[nn * 64 + off] = val;
        }
        __syncthreads();

        int n = ng + nl;
        const float* ms = sMid + nl * 256;       // 64 floats
        const float* mv = sMid + nl * 256 + 64;  // 192 floats = [3][64]
        float cs = 0.f, cv0 = 0.f, cv1 = 0.f, cv2 = 0.f;
#pragma unroll 8
        for (int u = 0; u < 64; ++u) {
            float ws = sW2s[u * 32 + v];
            float wv = sW2v[u * 32 + v];
            cs  += ms[u] * ws;
            cv0 += mv[u]       * wv;
            cv1 += mv[64 + u]  * wv;
            cv2 += mv[128 + u] * wv;
        }
        const float SC = SIN_A * INV_MID * INV_NB;
        out[n * 32 + v] = COS_A * g_ss[n * 32 + v] + SC * cs;
        float* outv = out + NNODE * 32;
        int b = (n * 32 + v) * 3;
        outv[b + 0] = COS_A * g_sv[b + 0] + SC * cv0;
        outv[b + 1] = COS_A * g_sv[b + 1] + SC * cv1;
        outv[b + 2] = COS_A * g_sv[b + 2] + SC * cv2;
        __syncthreads();
    }
}

// ---------------- launch ----------------
extern "C" void kernel_launch(void* const* d_in, const int* in_sizes, int n_in,
                              void* d_out, int out_size) {
    const float *node_s, *node_v, *eattr_s, *eattr_v, *esa;
    const float *W1sf, *W1ss, *W1vf, *W1vs, *Wm0, *Wm1;
    const float *Wi0, *Wi1, *Wi2, *Wi3, *W2s, *W2v;
    const int *e_src, *e_dst;

    node_s  = (const float*)d_in[0];
    node_v  = (const float*)d_in[1];
    eattr_s = (const float*)d_in[2];
    eattr_v = (const float*)d_in[3];
    esa     = (const float*)d_in[4];
    if (in_sizes[5] == NEDGE) {
        e_src = (const int*)d_in[5];
        e_dst = (const int*)d_in[6];
        W1sf = (const float*)d_in[7];  W1ss = (const float*)d_in[8];
        W1vf = (const float*)d_in[9];  W1vs = (const float*)d_in[10];
        Wm0  = (const float*)d_in[11]; Wm1  = (const float*)d_in[12];
        Wi0  = (const float*)d_in[13]; Wi1  = (const float*)d_in[14];
        Wi2  = (const float*)d_in[15]; Wi3  = (const float*)d_in[16];
        W2s  = (const float*)d_in[17]; W2v  = (const float*)d_in[18];
    } else {
        W1sf = (const float*)d_in[5];  W1ss = (const float*)d_in[6];
        W1vf = (const float*)d_in[7];  W1vs = (const float*)d_in[8];
        Wm0  = (const float*)d_in[9];  Wm1  = (const float*)d_in[10];
        Wi0  = (const float*)d_in[11]; Wi1  = (const float*)d_in[12];
        Wi2  = (const float*)d_in[13]; Wi3  = (const float*)d_in[14];
        W2s  = (const float*)d_in[15]; W2v  = (const float*)d_in[16];
        e_src = (const int*)d_in[17];
        e_dst = (const int*)d_in[18];
    }

    cudaFuncSetAttribute(edge_kernel,
                         cudaFuncAttributeMaxDynamicSharedMemorySize, SM_TOTAL);

    node_pre_kernel<<<625, 256>>>(node_s, node_v, W1sf, W1ss, W1vf, W1vs);

    edge_kernel<<<148, NTHR, SM_TOTAL>>>(
        esa, eattr_s, eattr_v, e_src, e_dst, Wm0, Wm1, Wi0, Wi1, Wi2, Wi3);

    node_post_kernel<<<625, 256>>>(W2s, W2v, (float*)d_out);
}